// round 15
// baseline (speedup 1.0000x reference)
#include <cuda_runtime.h>
#include <cuda_fp16.h>
#include <cstdint>

#define BB 4
#define SS 2048
#define EE 1024
#define PP 1024
#define HH 8
#define DD 128
#define HEAD_ELEMS (SS*DD)
#define BATCH_ELEMS (SS*PP)
#define NELEM (BB*SS*PP)
#define SOFTMAX_SCALE 0.3535533905932738f
#define EXP_C1 1.44269504f
#define EXP_C0 (-23.08312066f)   // -16 * log2(e)

typedef __half fp16;

__device__ fp16 g_Ehi[NELEM],  g_Elo[NELEM];
__device__ fp16 g_W1hi[EE*PP], g_W1lo[EE*PP];
__device__ fp16 g_W2hi[EE*PP], g_W2lo[EE*PP];
__device__ fp16 g_W3hi[EE*PP], g_W3lo[EE*PP];
__device__ fp16 g_Wohi[EE*PP];
__device__ fp16 g_Qhi[NELEM],  g_Qlo[NELEM];
__device__ fp16 g_Khi[NELEM],  g_Klo[NELEM];
__device__ fp16 g_Vhi[NELEM],  g_Vlo[NELEM];    // [bh][s][d]
__device__ fp16 g_Xhi[NELEM];                   // [b][s][p]
__device__ float g_cos[SS*64], g_sin[SS*64];

// ---------------- helpers ----------------
__device__ __forceinline__ uint32_t smem_u32(const void* p) {
    uint32_t a;
    asm("{ .reg .u64 t; cvta.to.shared.u64 t, %1; cvt.u32.u64 %0, t; }" : "=r"(a) : "l"(p));
    return a;
}

__device__ __forceinline__ void cpa16(uint32_t s, const void* g) {
    asm volatile("cp.async.cg.shared.global [%0], [%1], 16;" :: "r"(s), "l"(g));
}
#define CP_COMMIT() asm volatile("cp.async.commit_group;" ::: "memory")
#define CP_WAIT1()  asm volatile("cp.async.wait_group 1;" ::: "memory")
#define CP_WAIT0()  asm volatile("cp.async.wait_group 0;" ::: "memory")

__device__ __forceinline__ void split2(float x, fp16& h, fp16& l)
{
    h = __float2half_rn(x);
    l = __float2half_rn(x - __half2float(h));
}

__device__ __forceinline__ void split_pair(float a, float b, uint32_t& hp, uint32_t& lp)
{
    asm("cvt.rn.f16x2.f32 %0, %1, %2;" : "=r"(hp) : "f"(b), "f"(a));
    __half2 hh = *reinterpret_cast<__half2*>(&hp);
    float la = a - __half2float(__low2half(hh));
    float lb = b - __half2float(__high2half(hh));
    asm("cvt.rn.f16x2.f32 %0, %1, %2;" : "=r"(lp) : "f"(lb), "f"(la));
}

__device__ __forceinline__ uint32_t pack_pair(float a, float b)
{
    uint32_t r;
    asm("cvt.rn.f16x2.f32 %0, %1, %2;" : "=r"(r) : "f"(b), "f"(a));
    return r;
}

__device__ __forceinline__ float fexp(float s)
{
    float f = fmaf(s, EXP_C1, EXP_C0);
    float r;
    asm("ex2.approx.f32 %0, %1;" : "=f"(r) : "f"(f));
    return r;
}

__device__ __forceinline__ void ldsm4(uint32_t& r0, uint32_t& r1,
                                      uint32_t& r2, uint32_t& r3, uint32_t a)
{
    asm volatile("ldmatrix.sync.aligned.m8n8.x4.shared.b16 {%0,%1,%2,%3}, [%4];"
                 : "=r"(r0), "=r"(r1), "=r"(r2), "=r"(r3) : "r"(a));
}

__device__ __forceinline__ void ldsm4t(uint32_t& r0, uint32_t& r1,
                                       uint32_t& r2, uint32_t& r3, uint32_t a)
{
    asm volatile("ldmatrix.sync.aligned.m8n8.x4.trans.shared.b16 {%0,%1,%2,%3}, [%4];"
                 : "=r"(r0), "=r"(r1), "=r"(r2), "=r"(r3) : "r"(a));
}

__device__ __forceinline__ void mma_f16(float& c0, float& c1, float& c2, float& c3,
                                        uint32_t a0, uint32_t a1, uint32_t a2, uint32_t a3,
                                        uint32_t b0, uint32_t b1)
{
    asm volatile(
        "mma.sync.aligned.m16n8k16.row.col.f32.f16.f16.f32 "
        "{%0,%1,%2,%3}, {%4,%5,%6,%7}, {%8,%9}, {%0,%1,%2,%3};\n"
        : "+f"(c0), "+f"(c1), "+f"(c2), "+f"(c3)
        : "r"(a0), "r"(a1), "r"(a2), "r"(a3), "r"(b0), "r"(b1));
}

#define MMA3(C, AH0,AH1,AH2,AH3, AL0,AL1,AL2,AL3, BH0,BH1, BL0,BL1)          \
    do {                                                                      \
        mma_f16(C[0],C[1],C[2],C[3], AH0,AH1,AH2,AH3, BH0,BH1);               \
        mma_f16(C[0],C[1],C[2],C[3], AH0,AH1,AH2,AH3, BL0,BL1);               \
        mma_f16(C[0],C[1],C[2],C[3], AL0,AL1,AL2,AL3, BH0,BH1);               \
    } while (0)

#define MMA2(C, A0,A1,A2,A3, BH0,BH1, BL0,BL1)                                \
    do {                                                                      \
        mma_f16(C[0],C[1],C[2],C[3], A0,A1,A2,A3, BH0,BH1);                   \
        mma_f16(C[0],C[1],C[2],C[3], A0,A1,A2,A3, BL0,BL1);                   \
    } while (0)

// ---------------- aux kernels ----------------
__global__ void rope_table_kernel()
{
    int idx = blockIdx.x * blockDim.x + threadIdx.x;
    if (idx >= SS * 64) return;
    int dp = idx & 63;
    int s2 = idx >> 6;
    double inv = exp(-0.14391156831212787 * (double)dp);   // ln(10000)/64
    double ang = (double)s2 * inv;
    double sd, cd;
    sincos(ang, &sd, &cd);
    g_cos[idx] = (float)cd;
    g_sin[idx] = (float)sd;
}

__global__ void decomp_all_kernel(const float* __restrict__ emb,
                                  const float* __restrict__ W1,
                                  const float* __restrict__ W2,
                                  const float* __restrict__ W3,
                                  const float* __restrict__ Wo)
{
    int i = blockIdx.x * blockDim.x + threadIdx.x;
    if (i < NELEM) { split2(emb[i], g_Ehi[i], g_Elo[i]); return; }
    int j = i - NELEM;
    if (j >= 4 * EE * PP) return;
    int w = j >> 20, k = j & 1048575;
    if (w == 3) { g_Wohi[k] = __float2half_rn(Wo[k]); return; }
    float v; fp16 *h, *l;
    if (w == 0)      { v = W1[k]; h = g_W1hi; l = g_W1lo; }
    else if (w == 1) { v = W2[k]; h = g_W2hi; l = g_W2lo; }
    else             { v = W3[k]; h = g_W3hi; l = g_W3lo; }
    split2(v, h[k], l[k]);
}

// ---------------- QKV GEMM mainloop (TERMS = 3 or 2) ----------------
#define GEMM_SMEM 81920

template<int TERMS>
__device__ __forceinline__ void gemm_main(const fp16* Ah, const fp16* Al,
                                          const fp16* Bh, const fp16* Bl,
                                          float acc[4][4][4])
{
    extern __shared__ fp16 smem[];
    const int t = threadIdx.x, w = t >> 5, lane = t & 31;
    const int wm = (w >> 2) * 64, wn = (w & 3) * 32;
    uint32_t smB = smem_u32(smem);

    const int arow  = lane & 15, ahalf = lane >> 4;
    const int brow  = ((lane & 16) >> 1) + (lane & 7);
    const int bhalf = (lane >> 3) & 1;
    const uint32_t aBase = smB + (uint32_t)(wm + arow) * 80 + (uint32_t)ahalf * 16;
    const uint32_t bBase = smB + 20480 + (uint32_t)(wn + brow) * 80 + (uint32_t)bhalf * 16;

#pragma unroll
    for (int mt = 0; mt < 4; mt++)
#pragma unroll
        for (int nt = 0; nt < 4; nt++)
#pragma unroll
            for (int i = 0; i < 4; i++) acc[mt][nt][i] = 0.0f;

    const fp16* gp[4] = {Ah, Al, Bh, Bl};

    auto prefetch = [&](int c, int st) {
        int k0 = c * 32;
#pragma unroll
        for (int p = 0; p < 4; p++) {
            if (TERMS == 2 && p == 1) continue;
#pragma unroll
            for (int j = 0; j < 2; j++) {
                int fi = t + 256 * j;
                int row = fi >> 2, c8 = (fi & 3) * 8;
                cpa16(smB + st * 40960 + p * 10240 + (row * 40 + c8) * 2,
                      gp[p] + (size_t)row * 1024 + k0 + c8);
            }
        }
    };

    prefetch(0, 0);
    CP_COMMIT();

    for (int c = 0; c < 32; c++) {
        int sb = c & 1;
        __syncthreads();
        if (c + 1 < 32) { prefetch(c + 1, sb ^ 1); CP_COMMIT(); CP_WAIT1(); }
        else CP_WAIT0();
        __syncthreads();
        uint32_t u0 = sb * 40960;
#pragma unroll
        for (int ks = 0; ks < 2; ks++) {
            uint32_t ah[4][4], al[4][4];
#pragma unroll
            for (int mt = 0; mt < 4; mt++) {
                uint32_t ao = aBase + u0 + mt * 1280 + ks * 32;
                ldsm4(ah[mt][0], ah[mt][1], ah[mt][2], ah[mt][3], ao);
                if (TERMS == 3)
                    ldsm4(al[mt][0], al[mt][1], al[mt][2], al[mt][3], ao + 10240);
            }
            uint32_t bh[4][2], bl[4][2];
#pragma unroll
            for (int ntp = 0; ntp < 2; ntp++) {
                uint32_t bo = bBase + u0 + ntp * 1280 + ks * 32;
                ldsm4(bh[2*ntp][0], bh[2*ntp][1], bh[2*ntp+1][0], bh[2*ntp+1][1], bo);
                ldsm4(bl[2*ntp][0], bl[2*ntp][1], bl[2*ntp+1][0], bl[2*ntp+1][1], bo + 10240);
            }
#pragma unroll
            for (int mt = 0; mt < 4; mt++)
#pragma unroll
                for (int nt = 0; nt < 4; nt++) {
                    if (TERMS == 3)
                        MMA3(acc[mt][nt],
                             ah[mt][0], ah[mt][1], ah[mt][2], ah[mt][3],
                             al[mt][0], al[mt][1], al[mt][2], al[mt][3],
                             bh[nt][0], bh[nt][1], bl[nt][0], bl[nt][1]);
                    else
                        MMA2(acc[mt][nt],
                             ah[mt][0], ah[mt][1], ah[mt][2], ah[mt][3],
                             bh[nt][0], bh[nt][1], bl[nt][0], bl[nt][1]);
                }
        }
    }
}

// QKV: z=0 Q (rope+scale+split, 3-term), z=1 K (3-term), z=2 V (2-term)
__global__ __launch_bounds__(256, 2) void qkv_gemm_kernel()
{
    const int z = blockIdx.z;
    const fp16 *Bh, *Bl;
    if (z == 0)      { Bh = g_W1hi; Bl = g_W1lo; }
    else if (z == 1) { Bh = g_W2hi; Bl = g_W2lo; }
    else             { Bh = g_W3hi; Bl = g_W3lo; }
    const int m0 = blockIdx.y * 128, n0 = blockIdx.x * 128;
    const int t = threadIdx.x, w = t >> 5, lane = t & 31;
    const int g = lane >> 2, tg = lane & 3;
    const int wm = (w >> 2) * 64, wn = (w & 3) * 32;

    float acc[4][4][4];
    if (z == 2) {
        gemm_main<2>(g_Ehi + (size_t)m0 * 1024, g_Elo + (size_t)m0 * 1024,
                     Bh + (size_t)n0 * 1024, Bl + (size_t)n0 * 1024, acc);
#pragma unroll
        for (int mt = 0; mt < 4; mt++) {
#pragma unroll
            for (int nt = 0; nt < 4; nt++) {
                int c = n0 + wn + nt * 8 + 2 * tg;
#pragma unroll
                for (int half = 0; half < 2; half++) {
                    int r = m0 + wm + mt * 16 + g + half * 8;
                    size_t F = (size_t)r * 1024 + c;
                    uint32_t hp, lp;
                    split_pair(acc[mt][nt][half*2], acc[mt][nt][half*2 + 1], hp, lp);
                    *reinterpret_cast<uint32_t*>(g_Vhi + F) = hp;
                    *reinterpret_cast<uint32_t*>(g_Vlo + F) = lp;
                }
            }
        }
        return;
    }

    gemm_main<3>(g_Ehi + (size_t)m0 * 1024, g_Elo + (size_t)m0 * 1024,
                 Bh + (size_t)n0 * 1024, Bl + (size_t)n0 * 1024, acc);

    fp16* Dh = (z == 0) ? g_Qhi : g_Khi;
    fp16* Dl = (z == 0) ? g_Qlo : g_Klo;
    const float scale = (z == 0) ? SOFTMAX_SCALE : 1.0f;
#pragma unroll
    for (int mt = 0; mt < 4; mt++) {
#pragma unroll
        for (int nt = 0; nt < 4; nt++) {
            int c = n0 + wn + nt * 8 + 2 * tg;
            int dp = (c & 127) >> 1;
#pragma unroll
            for (int half = 0; half < 2; half++) {
                int r = m0 + wm + mt * 16 + g + half * 8;
                size_t F = (size_t)r * 1024 + c;
                int s2v = (int)((F >> 7) & 2047);
                int ti = s2v * 64 + dp;
                float cs = g_cos[ti], sn = g_sin[ti];
                float x = acc[mt][nt][half * 2], y = acc[mt][nt][half * 2 + 1];
                float rx = (x * cs - y * sn) * scale;
                float ry = (y * cs + x * sn) * scale;
                uint32_t hp, lp;
                split_pair(rx, ry, hp, lp);
                *reinterpret_cast<uint32_t*>(Dh + F) = hp;
                *reinterpret_cast<uint32_t*>(Dl + F) = lp;
            }
        }
    }
}

// ---------------- output GEMM (1-term fp16) ----------------
#define OUT_SMEM 37888

__global__ __launch_bounds__(256, 2) void out_gemm_kernel(float* __restrict__ out)
{
    extern __shared__ fp16 smem[];
    const size_t bc = blockIdx.z;
    const int m0 = blockIdx.y * 128, n0 = blockIdx.x * 128;
    const int t = threadIdx.x, w = t >> 5, lane = t & 31;
    const int g = lane >> 2, tg = lane & 3;
    const int wm = (w >> 2) * 64, wn = (w & 3) * 32;
    uint32_t smB = smem_u32(smem);

    const int arow  = lane & 15, ahalf = lane >> 4;
    const uint32_t aBase = smB + (uint32_t)(wm + arow) * 80 + (uint32_t)ahalf * 16;
    const int btrow = (lane & 7) + ((lane >> 3) & 1) * 8;
    const int btcol = (lane >> 4) * 8;
    const uint32_t bTBase = smB + 10240 + (uint32_t)btrow * 272 + (uint32_t)btcol * 2;

    const fp16* Ah = g_Wohi + (size_t)m0 * 1024;
    const fp16* Xh = g_Xhi + bc * 1048576;

    float acc[4][4][4];
#pragma unroll
    for (int mt = 0; mt < 4; mt++)
#pragma unroll
        for (int nt = 0; nt < 4; nt++)
#pragma unroll
            for (int i = 0; i < 4; i++) acc[mt][nt][i] = 0.0f;

    auto prefetch = [&](int c, int st) {
        int k0 = c * 32;
#pragma unroll
        for (int j = 0; j < 2; j++) {
            int fi = t + 256 * j;
            int row = fi >> 2, c8 = (fi & 3) * 8;
            cpa16(smB + st * 18944 + (row * 40 + c8) * 2,
                  Ah + (size_t)row * 1024 + k0 + c8);
        }
#pragma unroll
        for (int j = 0; j < 2; j++) {
            int fi = t + 256 * j;
            int row = fi >> 4, c8 = (fi & 15) * 8;
            cpa16(smB + st * 18944 + 10240 + (row * 136 + c8) * 2,
                  Xh + (size_t)(k0 + row) * 1024 + n0 + c8);
        }
    };

    prefetch(0, 0);
    CP_COMMIT();

    for (int c = 0; c < 32; c++) {
        int sb = c & 1;
        __syncthreads();
        if (c + 1 < 32) { prefetch(c + 1, sb ^ 1); CP_COMMIT(); CP_WAIT1(); }
        else CP_WAIT0();
        __syncthreads();
        uint32_t u0 = sb * 18944;
#pragma unroll
        for (int ks = 0; ks < 2; ks++) {
            uint32_t ah[4][4];
#pragma unroll
            for (int mt = 0; mt < 4; mt++) {
                uint32_t ao = aBase + u0 + mt * 1280 + ks * 32;
                ldsm4(ah[mt][0], ah[mt][1], ah[mt][2], ah[mt][3], ao);
            }
            uint32_t bh[4][2];
#pragma unroll
            for (int ntp = 0; ntp < 2; ntp++) {
                uint32_t bo = bTBase + u0 + ks * 4352 + (wn + ntp * 16) * 2;
                ldsm4t(bh[2*ntp][0], bh[2*ntp][1], bh[2*ntp+1][0], bh[2*ntp+1][1], bo);
            }
#pragma unroll
            for (int mt = 0; mt < 4; mt++)
#pragma unroll
                for (int nt = 0; nt < 4; nt++)
                    mma_f16(acc[mt][nt][0], acc[mt][nt][1], acc[mt][nt][2], acc[mt][nt][3],
                            ah[mt][0], ah[mt][1], ah[mt][2], ah[mt][3],
                            bh[nt][0], bh[nt][1]);
        }
    }

    float* Ob = out + bc * 1048576;
#pragma unroll
    for (int mt = 0; mt < 4; mt++) {
        int r0 = m0 + wm + mt * 16 + g;
#pragma unroll
        for (int nt = 0; nt < 4; nt++) {
            int cc = n0 + wn + nt * 8 + 2 * tg;
            *reinterpret_cast<float2*>(Ob + (size_t)r0 * PP + cc) =
                make_float2(acc[mt][nt][0], acc[mt][nt][1]);
            *reinterpret_cast<float2*>(Ob + (size_t)(r0 + 8) * PP + cc) =
                make_float2(acc[mt][nt][2], acc[mt][nt][3]);
        }
    }
}

// ---------------- flash attention: pipelined S(kt) | PV(kt-1) | softmax(kt) ----------
// 128 threads, 2 CTAs/SM, Br=64, Bc=32, 3-stage K/V smem.
// stage st (34816 B): Khi@0, Klo@8704, Vhi@17408, Vlo@26112.
#define FL_STAGE 34816
#define FL_BYTES (3 * FL_STAGE)   // 104448

__global__ __launch_bounds__(128, 2) void flash_kernel()
{
    extern __shared__ char sm[];
    const int bh = blockIdx.y, q0 = blockIdx.x * 64;
    const int t = threadIdx.x, w = t >> 5, lane = t & 31;
    const int g = lane >> 2, tg = lane & 3;
    const int qb = w * 16;
    uint32_t smB = smem_u32(sm);

    const int brow  = ((lane & 16) >> 1) + (lane & 7);
    const int bhalf = (lane >> 3) & 1;
    const uint32_t kBase = smB + (uint32_t)brow * 272 + (uint32_t)bhalf * 16;
    const int btrow = (lane & 7) + ((lane >> 3) & 1) * 8;
    const int btcol = (lane >> 4) * 8;
    const uint32_t vBase = smB + 17408 + (uint32_t)btrow * 272 + (uint32_t)btcol * 2;

    const fp16* Qh = g_Qhi + (size_t)bh * HEAD_ELEMS + (size_t)q0 * DD;
    const fp16* Ql = g_Qlo + (size_t)bh * HEAD_ELEMS + (size_t)q0 * DD;
    const fp16* Kh = g_Khi + (size_t)bh * HEAD_ELEMS;
    const fp16* Kl = g_Klo + (size_t)bh * HEAD_ELEMS;
    const fp16* Vh = g_Vhi + (size_t)bh * HEAD_ELEMS;
    const fp16* Vl = g_Vlo + (size_t)bh * HEAD_ELEMS;

    uint32_t qa[8][8];
    {
        int ra = qb + g, rb2 = qb + g + 8;
#pragma unroll
        for (int kd = 0; kd < 8; kd++) {
            int c0 = kd * 16 + 2 * tg;
            qa[kd][0] = *reinterpret_cast<const uint32_t*>(Qh + ra  * 128 + c0);
            qa[kd][1] = *reinterpret_cast<const uint32_t*>(Qh + rb2 * 128 + c0);
            qa[kd][2] = *reinterpret_cast<const uint32_t*>(Qh + ra  * 128 + c0 + 8);
            qa[kd][3] = *reinterpret_cast<const uint32_t*>(Qh + rb2 * 128 + c0 + 8);
            qa[kd][4] = *reinterpret_cast<const uint32_t*>(Ql + ra  * 128 + c0);
            qa[kd][5] = *reinterpret_cast<const uint32_t*>(Ql + rb2 * 128 + c0);
            qa[kd][6] = *reinterpret_cast<const uint32_t*>(Ql + ra  * 128 + c0 + 8);
            qa[kd][7] = *reinterpret_cast<const uint32_t*>(Ql + rb2 * 128 + c0 + 8);
        }
    }

    auto prefetch = [&](int kt, int st) {
#pragma unroll
        for (int q = 0; q < 4; q++) {   // {Khi,Klo,Vhi,Vlo}
            const fp16* src = (q == 0) ? Kh : (q == 1) ? Kl : (q == 2) ? Vh : Vl;
            uint32_t sbase = smB + st * FL_STAGE + q * 8704;
#pragma unroll
            for (int j = 0; j < 4; j++) {
                int fi = t + 128 * j;          // 32 rows x 16 chunks
                int r = fi >> 4, i = fi & 15;
                cpa16(sbase + (r * 136 + i * 8) * 2,
                      src + (size_t)(kt * 32 + r) * 128 + i * 8);
            }
        }
    };

    float oc[16][4];
#pragma unroll
    for (int nt = 0; nt < 16; nt++)
#pragma unroll
        for (int i = 0; i < 4; i++) oc[nt][i] = 0.0f;
    float l0r = 0.0f, l1r = 0.0f;

    uint32_t pA[8], pB[8];   // P fragments: [kc*4 + {a0,a1,a2,a3}]

    prefetch(0, 0);
    CP_COMMIT();

// One pipelined tile: S(KT) from stage SCUR; PV(KT-1) from stage SPREV using PFR;
// softmax(KT) -> PFW.
#define FL_TILE(KT, SCUR, SPREV, PFR, PFW, DOPV)                              \
    {                                                                         \
        __syncthreads();                                                      \
        if ((KT) + 1 < 64) {                                                  \
            int snx = (SCUR) + 1; if (snx == 3) snx = 0;                      \
            prefetch((KT) + 1, snx); CP_COMMIT(); CP_WAIT1();                 \
        } else CP_WAIT0();                                                    \
        __syncthreads();                                                      \
        const uint32_t kS = kBase + (SCUR) * FL_STAGE;                        \
        const uint32_t vS = vBase + (SPREV) * FL_STAGE;                       \
        float sc[4][4];                                                       \
        _Pragma("unroll")                                                     \
        for (int nt = 0; nt < 4; nt++)                                        \
            _Pragma("unroll")                                                 \
            for (int i = 0; i < 4; i++) sc[nt][i] = 0.0f;                     \
        _Pragma("unroll")                                                     \
        for (int kd = 0; kd < 8; kd++) {                                      \
            uint32_t ah0 = qa[kd][0], ah1 = qa[kd][1], ah2 = qa[kd][2], ah3 = qa[kd][3]; \
            uint32_t al0 = qa[kd][4], al1 = qa[kd][5], al2 = qa[kd][6], al3 = qa[kd][7]; \
            _Pragma("unroll")                                                 \
            for (int ntp = 0; ntp < 2; ntp++) {                               \
                uint32_t h0, h1, h2, h3, l0, l1, l2, l3;                      \
                uint32_t ko = kS + ntp * 4352 + kd * 32;                      \
                ldsm4(h0, h1, h2, h3, ko);                                    \
                ldsm4(l0, l1, l2, l3, ko + 8704);                             \
                MMA3(sc[2*ntp],   ah0, ah1, ah2, ah3, al0, al1, al2, al3, h0, h1, l0, l1); \
                MMA3(sc[2*ntp+1], ah0, ah1, ah2, ah3, al0, al1, al2, al3, h2, h3, l2, l3); \
            }                                                                 \
        }                                                                     \
        if (DOPV) {                                                           \
            _Pragma("unroll")                                                 \
            for (int kc = 0; kc < 2; kc++) {                                  \
                uint32_t a0 = PFR[kc*4+0], a1 = PFR[kc*4+1];                  \
                uint32_t a2 = PFR[kc*4+2], a3 = PFR[kc*4+3];                  \
                _Pragma("unroll")                                             \
                for (int ntp = 0; ntp < 8; ntp++) {                           \
                    uint32_t h0, h1, h2, h3, l0, l1, l2, l3;                  \
                    uint32_t vo = vS + kc * 4352 + ntp * 32;                  \
                    ldsm4t(h0, h1, h2, h3, vo);                               \
                    ldsm4t(l0, l1, l2, l3, vo + 8704);                        \
                    MMA2(oc[2*ntp],   a0, a1, a2, a3, h0, h1, l0, l1);        \
                    MMA2(oc[2*ntp+1], a0, a1, a2, a3, h2, h3, l2, l3);        \
                }                                                             \
            }                                                                 \
        }                                                                     \
        _Pragma("unroll")                                                     \
        for (int kc = 0; kc < 2; kc++) {                                      \
            float e00 = fexp(sc[2*kc][0]);                                    \
            float e01 = fexp(sc[2*kc][1]);                                    \
            float e10 = fexp(sc[2*kc][2]);                                    \
            float e11 = fexp(sc[2*kc][3]);                                    \
            float f00 = fexp(sc[2*kc+1][0]);                                  \
            float f01 = fexp(sc[2*kc+1][1]);                                  \
            float f10 = fexp(sc[2*kc+1][2]);                                  \
            float f11 = fexp(sc[2*kc+1][3]);                                  \
            l0r += (e00 + e01) + (f00 + f01);                                 \
            l1r += (e10 + e11) + (f10 + f11);                                 \
            PFW[kc*4+0] = pack_pair(e00, e01);                                \
            PFW[kc*4+1] = pack_pair(e10, e11);                                \
            PFW[kc*4+2] = pack_pair(f00, f01);                                \
            PFW[kc*4+3] = pack_pair(f10, f11);                                \
        }                                                                     \
    }

    // kt=0: no PV; writes pA.  Then pairs: odd reads pA writes pB, even reads pB writes pA.
    int sCur = 0;
    FL_TILE(0, 0, 2, pB, pA, false);
    sCur = 1;
    for (int it = 0; it < 31; it++) {
        int kt = 2 * it + 1;
        int sP = sCur - 1; if (sP < 0) sP = 2;
        FL_TILE(kt, sCur, sP, pA, pB, true);
        int sN = sCur + 1; if (sN == 3) sN = 0;
        FL_TILE(kt + 1, sN, sCur, pB, pA, true);
        sCur = sN + 1; if (sCur == 3) sCur = 0;
    }
    {   // kt = 63 (odd): reads pA, writes pB
        int sP = sCur - 1; if (sP < 0) sP = 2;
        FL_TILE(63, sCur, sP, pA, pB, true);
    }
    // final PV(63): V stage = 63 % 3 = 0, P in pB
    {
        const uint32_t vS = vBase + 0 * FL_STAGE;
#pragma unroll
        for (int kc = 0; kc < 2; kc++) {
            uint32_t a0 = pB[kc*4+0], a1 = pB[kc*4+1];
            uint32_t a2 = pB[kc*4+2], a3 = pB[kc*4+3];
#pragma unroll
            for (int ntp = 0; ntp < 8; ntp++) {
                uint32_t h0, h1, h2, h3, l0, l1, l2, l3;
                uint32_t vo = vS + kc * 4352 + ntp * 32;
                ldsm4t(h0, h1, h2, h3, vo);
                ldsm4t(l0, l1, l2, l3, vo + 8704);
                MMA2(oc[2*ntp],   a0, a1, a2, a3, h0, h1, l0, l1);
                MMA2(oc[2*ntp+1], a0, a1, a2, a3, h2, h3, l2, l3);
            }
        }
    }

    l0r += __shfl_xor_sync(0xffffffffu, l0r, 1);
    l0r += __shfl_xor_sync(0xffffffffu, l0r, 2);
    l1r += __shfl_xor_sync(0xffffffffu, l1r, 1);
    l1r += __shfl_xor_sync(0xffffffffu, l1r, 2);

    // epilogue: normalize, write X-hi
    const int b = bh >> 3, h = bh & 7;
    float inv0 = 1.0f / l0r;
    float inv1 = 1.0f / l1r;
    size_t Xo = (size_t)b * BATCH_ELEMS + (size_t)q0 * PP + h * DD;
    int r0 = qb + g;
#pragma unroll
    for (int nt = 0; nt < 16; nt++) {
        int cc = nt * 8 + 2 * tg;
        size_t F0 = Xo + (size_t)r0 * PP + cc;
        size_t F1 = Xo + (size_t)(r0 + 8) * PP + cc;
        *reinterpret_cast<uint32_t*>(g_Xhi + F0) =
            pack_pair(oc[nt][0] * inv0, oc[nt][1] * inv0);
        *reinterpret_cast<uint32_t*>(g_Xhi + F1) =
            pack_pair(oc[nt][2] * inv1, oc[nt][3] * inv1);
    }
}

// ---------------- launch ----------------
extern "C" void kernel_launch(void* const* d_in, const int* in_sizes, int n_in,
                              void* d_out, int out_size)
{
    const float* emb = (const float*)d_in[0];
    const float* W1  = (const float*)d_in[1];
    const float* W2  = (const float*)d_in[2];
    const float* W3  = (const float*)d_in[3];
    const float* Wo  = (const float*)d_in[4];
    float* out = (float*)d_out;
    (void)in_sizes; (void)n_in; (void)out_size;

    cudaFuncSetAttribute(qkv_gemm_kernel, cudaFuncAttributeMaxDynamicSharedMemorySize, GEMM_SMEM);
    cudaFuncSetAttribute(out_gemm_kernel, cudaFuncAttributeMaxDynamicSharedMemorySize, OUT_SMEM);
    cudaFuncSetAttribute(flash_kernel,    cudaFuncAttributeMaxDynamicSharedMemorySize, FL_BYTES);

    rope_table_kernel<<<512, 256>>>();                                        // 0
    decomp_all_kernel<<<(NELEM + 4 * EE * PP + 255) / 256, 256>>>(emb, W1, W2, W3, Wo); // 1
    qkv_gemm_kernel<<<dim3(8, 64, 3), 256, GEMM_SMEM>>>();                    // 2
    flash_kernel<<<dim3(32, 32), 128, FL_BYTES>>>();                          // 3  <- ncu window
    out_gemm_kernel<<<dim3(8, 8, 8), 256, OUT_SMEM>>>(out);                   // 4
}

// round 16
// speedup vs baseline: 1.1141x; 1.1141x over previous
#include <cuda_runtime.h>
#include <cuda_fp16.h>
#include <cstdint>

#define BB 4
#define SS 2048
#define EE 1024
#define PP 1024
#define HH 8
#define DD 128
#define HEAD_ELEMS (SS*DD)
#define BATCH_ELEMS (SS*PP)
#define NELEM (BB*SS*PP)
#define SOFTMAX_SCALE 0.3535533905932738f
#define EXP_C1 1.44269504f
#define EXP_C0 (-23.08312066f)   // -16 * log2(e)

typedef __half fp16;

__device__ fp16 g_Ehi[NELEM],  g_Elo[NELEM];
__device__ fp16 g_W1hi[EE*PP], g_W1lo[EE*PP];
__device__ fp16 g_W2hi[EE*PP], g_W2lo[EE*PP];
__device__ fp16 g_W3hi[EE*PP], g_W3lo[EE*PP];
__device__ fp16 g_Wohi[EE*PP];
__device__ fp16 g_Qhi[NELEM],  g_Qlo[NELEM];
__device__ fp16 g_Khi[NELEM];                   // K-lo dropped (S 2-term)
__device__ fp16 g_Klo[NELEM];                   // still written by qkv (3-term proj)
__device__ fp16 g_Vhi[NELEM],  g_Vlo[NELEM];    // [bh][s][d]
__device__ fp16 g_Xhi[NELEM];                   // [b][s][p]
__device__ float g_cos[SS*64], g_sin[SS*64];

// ---------------- helpers ----------------
__device__ __forceinline__ uint32_t smem_u32(const void* p) {
    uint32_t a;
    asm("{ .reg .u64 t; cvta.to.shared.u64 t, %1; cvt.u32.u64 %0, t; }" : "=r"(a) : "l"(p));
    return a;
}

__device__ __forceinline__ void cpa16(uint32_t s, const void* g) {
    asm volatile("cp.async.cg.shared.global [%0], [%1], 16;" :: "r"(s), "l"(g));
}
#define CP_COMMIT() asm volatile("cp.async.commit_group;" ::: "memory")
#define CP_WAIT1()  asm volatile("cp.async.wait_group 1;" ::: "memory")
#define CP_WAIT0()  asm volatile("cp.async.wait_group 0;" ::: "memory")

__device__ __forceinline__ void split2(float x, fp16& h, fp16& l)
{
    h = __float2half_rn(x);
    l = __float2half_rn(x - __half2float(h));
}

__device__ __forceinline__ void split_pair(float a, float b, uint32_t& hp, uint32_t& lp)
{
    asm("cvt.rn.f16x2.f32 %0, %1, %2;" : "=r"(hp) : "f"(b), "f"(a));
    __half2 hh = *reinterpret_cast<__half2*>(&hp);
    float la = a - __half2float(__low2half(hh));
    float lb = b - __half2float(__high2half(hh));
    asm("cvt.rn.f16x2.f32 %0, %1, %2;" : "=r"(lp) : "f"(lb), "f"(la));
}

__device__ __forceinline__ uint32_t pack_pair(float a, float b)
{
    uint32_t r;
    asm("cvt.rn.f16x2.f32 %0, %1, %2;" : "=r"(r) : "f"(b), "f"(a));
    return r;
}

__device__ __forceinline__ float fexp(float s)
{
    float f = fmaf(s, EXP_C1, EXP_C0);
    float r;
    asm("ex2.approx.f32 %0, %1;" : "=f"(r) : "f"(f));
    return r;
}

__device__ __forceinline__ void ldsm4(uint32_t& r0, uint32_t& r1,
                                      uint32_t& r2, uint32_t& r3, uint32_t a)
{
    asm volatile("ldmatrix.sync.aligned.m8n8.x4.shared.b16 {%0,%1,%2,%3}, [%4];"
                 : "=r"(r0), "=r"(r1), "=r"(r2), "=r"(r3) : "r"(a));
}

__device__ __forceinline__ void ldsm4t(uint32_t& r0, uint32_t& r1,
                                       uint32_t& r2, uint32_t& r3, uint32_t a)
{
    asm volatile("ldmatrix.sync.aligned.m8n8.x4.trans.shared.b16 {%0,%1,%2,%3}, [%4];"
                 : "=r"(r0), "=r"(r1), "=r"(r2), "=r"(r3) : "r"(a));
}

__device__ __forceinline__ void mma_f16(float& c0, float& c1, float& c2, float& c3,
                                        uint32_t a0, uint32_t a1, uint32_t a2, uint32_t a3,
                                        uint32_t b0, uint32_t b1)
{
    asm volatile(
        "mma.sync.aligned.m16n8k16.row.col.f32.f16.f16.f32 "
        "{%0,%1,%2,%3}, {%4,%5,%6,%7}, {%8,%9}, {%0,%1,%2,%3};\n"
        : "+f"(c0), "+f"(c1), "+f"(c2), "+f"(c3)
        : "r"(a0), "r"(a1), "r"(a2), "r"(a3), "r"(b0), "r"(b1));
}

#define MMA3(C, AH0,AH1,AH2,AH3, AL0,AL1,AL2,AL3, BH0,BH1, BL0,BL1)          \
    do {                                                                      \
        mma_f16(C[0],C[1],C[2],C[3], AH0,AH1,AH2,AH3, BH0,BH1);               \
        mma_f16(C[0],C[1],C[2],C[3], AH0,AH1,AH2,AH3, BL0,BL1);               \
        mma_f16(C[0],C[1],C[2],C[3], AL0,AL1,AL2,AL3, BH0,BH1);               \
    } while (0)

// two B planes, one A set
#define MMA2(C, A0,A1,A2,A3, BH0,BH1, BL0,BL1)                                \
    do {                                                                      \
        mma_f16(C[0],C[1],C[2],C[3], A0,A1,A2,A3, BH0,BH1);                   \
        mma_f16(C[0],C[1],C[2],C[3], A0,A1,A2,A3, BL0,BL1);                   \
    } while (0)

// two A sets, one B plane (flash S 2-term)
#define MMA2A(C, AH0,AH1,AH2,AH3, AL0,AL1,AL2,AL3, B0,B1)                     \
    do {                                                                      \
        mma_f16(C[0],C[1],C[2],C[3], AH0,AH1,AH2,AH3, B0,B1);                 \
        mma_f16(C[0],C[1],C[2],C[3], AL0,AL1,AL2,AL3, B0,B1);                 \
    } while (0)

// ---------------- aux kernels ----------------
__global__ void rope_table_kernel()
{
    int idx = blockIdx.x * blockDim.x + threadIdx.x;
    if (idx >= SS * 64) return;
    int dp = idx & 63;
    int s2 = idx >> 6;
    double inv = exp(-0.14391156831212787 * (double)dp);   // ln(10000)/64
    double ang = (double)s2 * inv;
    double sd, cd;
    sincos(ang, &sd, &cd);
    g_cos[idx] = (float)cd;
    g_sin[idx] = (float)sd;
}

__global__ void decomp_all_kernel(const float* __restrict__ emb,
                                  const float* __restrict__ W1,
                                  const float* __restrict__ W2,
                                  const float* __restrict__ W3,
                                  const float* __restrict__ Wo)
{
    int i = blockIdx.x * blockDim.x + threadIdx.x;
    if (i < NELEM) { split2(emb[i], g_Ehi[i], g_Elo[i]); return; }
    int j = i - NELEM;
    if (j >= 4 * EE * PP) return;
    int w = j >> 20, k = j & 1048575;
    if (w == 3) { g_Wohi[k] = __float2half_rn(Wo[k]); return; }
    float v; fp16 *h, *l;
    if (w == 0)      { v = W1[k]; h = g_W1hi; l = g_W1lo; }
    else if (w == 1) { v = W2[k]; h = g_W2hi; l = g_W2lo; }
    else             { v = W3[k]; h = g_W3hi; l = g_W3lo; }
    split2(v, h[k], l[k]);
}

// ---------------- QKV GEMM mainloop (TERMS = 3 or 2) ----------------
#define GEMM_SMEM 81920

template<int TERMS>
__device__ __forceinline__ void gemm_main(const fp16* Ah, const fp16* Al,
                                          const fp16* Bh, const fp16* Bl,
                                          float acc[4][4][4])
{
    extern __shared__ fp16 smem[];
    const int t = threadIdx.x, w = t >> 5, lane = t & 31;
    const int wm = (w >> 2) * 64, wn = (w & 3) * 32;
    uint32_t smB = smem_u32(smem);

    const int arow  = lane & 15, ahalf = lane >> 4;
    const int brow  = ((lane & 16) >> 1) + (lane & 7);
    const int bhalf = (lane >> 3) & 1;
    const uint32_t aBase = smB + (uint32_t)(wm + arow) * 80 + (uint32_t)ahalf * 16;
    const uint32_t bBase = smB + 20480 + (uint32_t)(wn + brow) * 80 + (uint32_t)bhalf * 16;

#pragma unroll
    for (int mt = 0; mt < 4; mt++)
#pragma unroll
        for (int nt = 0; nt < 4; nt++)
#pragma unroll
            for (int i = 0; i < 4; i++) acc[mt][nt][i] = 0.0f;

    const fp16* gp[4] = {Ah, Al, Bh, Bl};

    auto prefetch = [&](int c, int st) {
        int k0 = c * 32;
#pragma unroll
        for (int p = 0; p < 4; p++) {
            if (TERMS == 2 && p == 1) continue;
#pragma unroll
            for (int j = 0; j < 2; j++) {
                int fi = t + 256 * j;
                int row = fi >> 2, c8 = (fi & 3) * 8;
                cpa16(smB + st * 40960 + p * 10240 + (row * 40 + c8) * 2,
                      gp[p] + (size_t)row * 1024 + k0 + c8);
            }
        }
    };

    prefetch(0, 0);
    CP_COMMIT();

    for (int c = 0; c < 32; c++) {
        int sb = c & 1;
        __syncthreads();
        if (c + 1 < 32) { prefetch(c + 1, sb ^ 1); CP_COMMIT(); CP_WAIT1(); }
        else CP_WAIT0();
        __syncthreads();
        uint32_t u0 = sb * 40960;
#pragma unroll
        for (int ks = 0; ks < 2; ks++) {
            uint32_t ah[4][4], al[4][4];
#pragma unroll
            for (int mt = 0; mt < 4; mt++) {
                uint32_t ao = aBase + u0 + mt * 1280 + ks * 32;
                ldsm4(ah[mt][0], ah[mt][1], ah[mt][2], ah[mt][3], ao);
                if (TERMS == 3)
                    ldsm4(al[mt][0], al[mt][1], al[mt][2], al[mt][3], ao + 10240);
            }
            uint32_t bh[4][2], bl[4][2];
#pragma unroll
            for (int ntp = 0; ntp < 2; ntp++) {
                uint32_t bo = bBase + u0 + ntp * 1280 + ks * 32;
                ldsm4(bh[2*ntp][0], bh[2*ntp][1], bh[2*ntp+1][0], bh[2*ntp+1][1], bo);
                ldsm4(bl[2*ntp][0], bl[2*ntp][1], bl[2*ntp+1][0], bl[2*ntp+1][1], bo + 10240);
            }
#pragma unroll
            for (int mt = 0; mt < 4; mt++)
#pragma unroll
                for (int nt = 0; nt < 4; nt++) {
                    if (TERMS == 3)
                        MMA3(acc[mt][nt],
                             ah[mt][0], ah[mt][1], ah[mt][2], ah[mt][3],
                             al[mt][0], al[mt][1], al[mt][2], al[mt][3],
                             bh[nt][0], bh[nt][1], bl[nt][0], bl[nt][1]);
                    else
                        MMA2(acc[mt][nt],
                             ah[mt][0], ah[mt][1], ah[mt][2], ah[mt][3],
                             bh[nt][0], bh[nt][1], bl[nt][0], bl[nt][1]);
                }
        }
    }
}

// QKV: z=0 Q (rope+scale+split, 3-term), z=1 K (3-term), z=2 V (2-term)
__global__ __launch_bounds__(256, 2) void qkv_gemm_kernel()
{
    const int z = blockIdx.z;
    const fp16 *Bh, *Bl;
    if (z == 0)      { Bh = g_W1hi; Bl = g_W1lo; }
    else if (z == 1) { Bh = g_W2hi; Bl = g_W2lo; }
    else             { Bh = g_W3hi; Bl = g_W3lo; }
    const int m0 = blockIdx.y * 128, n0 = blockIdx.x * 128;
    const int t = threadIdx.x, w = t >> 5, lane = t & 31;
    const int g = lane >> 2, tg = lane & 3;
    const int wm = (w >> 2) * 64, wn = (w & 3) * 32;

    float acc[4][4][4];
    if (z == 2) {
        gemm_main<2>(g_Ehi + (size_t)m0 * 1024, g_Elo + (size_t)m0 * 1024,
                     Bh + (size_t)n0 * 1024, Bl + (size_t)n0 * 1024, acc);
#pragma unroll
        for (int mt = 0; mt < 4; mt++) {
#pragma unroll
            for (int nt = 0; nt < 4; nt++) {
                int c = n0 + wn + nt * 8 + 2 * tg;
#pragma unroll
                for (int half = 0; half < 2; half++) {
                    int r = m0 + wm + mt * 16 + g + half * 8;
                    size_t F = (size_t)r * 1024 + c;
                    uint32_t hp, lp;
                    split_pair(acc[mt][nt][half*2], acc[mt][nt][half*2 + 1], hp, lp);
                    *reinterpret_cast<uint32_t*>(g_Vhi + F) = hp;
                    *reinterpret_cast<uint32_t*>(g_Vlo + F) = lp;
                }
            }
        }
        return;
    }

    gemm_main<3>(g_Ehi + (size_t)m0 * 1024, g_Elo + (size_t)m0 * 1024,
                 Bh + (size_t)n0 * 1024, Bl + (size_t)n0 * 1024, acc);

    fp16* Dh = (z == 0) ? g_Qhi : g_Khi;
    fp16* Dl = (z == 0) ? g_Qlo : g_Klo;
    const float scale = (z == 0) ? SOFTMAX_SCALE : 1.0f;
#pragma unroll
    for (int mt = 0; mt < 4; mt++) {
#pragma unroll
        for (int nt = 0; nt < 4; nt++) {
            int c = n0 + wn + nt * 8 + 2 * tg;
            int dp = (c & 127) >> 1;
#pragma unroll
            for (int half = 0; half < 2; half++) {
                int r = m0 + wm + mt * 16 + g + half * 8;
                size_t F = (size_t)r * 1024 + c;
                int s2v = (int)((F >> 7) & 2047);
                int ti = s2v * 64 + dp;
                float cs = g_cos[ti], sn = g_sin[ti];
                float x = acc[mt][nt][half * 2], y = acc[mt][nt][half * 2 + 1];
                float rx = (x * cs - y * sn) * scale;
                float ry = (y * cs + x * sn) * scale;
                uint32_t hp, lp;
                split_pair(rx, ry, hp, lp);
                *reinterpret_cast<uint32_t*>(Dh + F) = hp;
                *reinterpret_cast<uint32_t*>(Dl + F) = lp;
            }
        }
    }
}

// ---------------- output GEMM (1-term fp16) ----------------
#define OUT_SMEM 37888

__global__ __launch_bounds__(256, 2) void out_gemm_kernel(float* __restrict__ out)
{
    extern __shared__ fp16 smem[];
    const size_t bc = blockIdx.z;
    const int m0 = blockIdx.y * 128, n0 = blockIdx.x * 128;
    const int t = threadIdx.x, w = t >> 5, lane = t & 31;
    const int g = lane >> 2, tg = lane & 3;
    const int wm = (w >> 2) * 64, wn = (w & 3) * 32;
    uint32_t smB = smem_u32(smem);

    const int arow  = lane & 15, ahalf = lane >> 4;
    const uint32_t aBase = smB + (uint32_t)(wm + arow) * 80 + (uint32_t)ahalf * 16;
    const int btrow = (lane & 7) + ((lane >> 3) & 1) * 8;
    const int btcol = (lane >> 4) * 8;
    const uint32_t bTBase = smB + 10240 + (uint32_t)btrow * 272 + (uint32_t)btcol * 2;

    const fp16* Ah = g_Wohi + (size_t)m0 * 1024;
    const fp16* Xh = g_Xhi + bc * 1048576;

    float acc[4][4][4];
#pragma unroll
    for (int mt = 0; mt < 4; mt++)
#pragma unroll
        for (int nt = 0; nt < 4; nt++)
#pragma unroll
            for (int i = 0; i < 4; i++) acc[mt][nt][i] = 0.0f;

    auto prefetch = [&](int c, int st) {
        int k0 = c * 32;
#pragma unroll
        for (int j = 0; j < 2; j++) {
            int fi = t + 256 * j;
            int row = fi >> 2, c8 = (fi & 3) * 8;
            cpa16(smB + st * 18944 + (row * 40 + c8) * 2,
                  Ah + (size_t)row * 1024 + k0 + c8);
        }
#pragma unroll
        for (int j = 0; j < 2; j++) {
            int fi = t + 256 * j;
            int row = fi >> 4, c8 = (fi & 15) * 8;
            cpa16(smB + st * 18944 + 10240 + (row * 136 + c8) * 2,
                  Xh + (size_t)(k0 + row) * 1024 + n0 + c8);
        }
    };

    prefetch(0, 0);
    CP_COMMIT();

    for (int c = 0; c < 32; c++) {
        int sb = c & 1;
        __syncthreads();
        if (c + 1 < 32) { prefetch(c + 1, sb ^ 1); CP_COMMIT(); CP_WAIT1(); }
        else CP_WAIT0();
        __syncthreads();
        uint32_t u0 = sb * 18944;
#pragma unroll
        for (int ks = 0; ks < 2; ks++) {
            uint32_t ah[4][4];
#pragma unroll
            for (int mt = 0; mt < 4; mt++) {
                uint32_t ao = aBase + u0 + mt * 1280 + ks * 32;
                ldsm4(ah[mt][0], ah[mt][1], ah[mt][2], ah[mt][3], ao);
            }
            uint32_t bh[4][2];
#pragma unroll
            for (int ntp = 0; ntp < 2; ntp++) {
                uint32_t bo = bTBase + u0 + ks * 4352 + (wn + ntp * 16) * 2;
                ldsm4t(bh[2*ntp][0], bh[2*ntp][1], bh[2*ntp+1][0], bh[2*ntp+1][1], bo);
            }
#pragma unroll
            for (int mt = 0; mt < 4; mt++)
#pragma unroll
                for (int nt = 0; nt < 4; nt++)
                    mma_f16(acc[mt][nt][0], acc[mt][nt][1], acc[mt][nt][2], acc[mt][nt][3],
                            ah[mt][0], ah[mt][1], ah[mt][2], ah[mt][3],
                            bh[nt][0], bh[nt][1]);
        }
    }

    float* Ob = out + bc * 1048576;
#pragma unroll
    for (int mt = 0; mt < 4; mt++) {
        int r0 = m0 + wm + mt * 16 + g;
#pragma unroll
        for (int nt = 0; nt < 4; nt++) {
            int cc = n0 + wn + nt * 8 + 2 * tg;
            *reinterpret_cast<float2*>(Ob + (size_t)r0 * PP + cc) =
                make_float2(acc[mt][nt][0], acc[mt][nt][1]);
            *reinterpret_cast<float2*>(Ob + (size_t)(r0 + 8) * PP + cc) =
                make_float2(acc[mt][nt][2], acc[mt][nt][3]);
        }
    }
}

// ---------------- flash attention: S 2-term (K hi-only), PV 2-term ----------------
// 128 threads, 2 CTAs/SM, Br=64, Bc=32, 2-stage smem.
// stage st (26112 B): Khi@0, Vhi@8704, Vlo@17408.
#define FL_STAGE 26112
#define FL_BYTES (2 * FL_STAGE)   // 52224

__global__ __launch_bounds__(128, 2) void flash_kernel()
{
    extern __shared__ char sm[];
    const int bh = blockIdx.y, q0 = blockIdx.x * 64;
    const int t = threadIdx.x, w = t >> 5, lane = t & 31;
    const int g = lane >> 2, tg = lane & 3;
    const int qb = w * 16;
    uint32_t smB = smem_u32(sm);

    const int brow  = ((lane & 16) >> 1) + (lane & 7);
    const int bhalf = (lane >> 3) & 1;
    const uint32_t kBase = smB + (uint32_t)brow * 272 + (uint32_t)bhalf * 16;
    const int btrow = (lane & 7) + ((lane >> 3) & 1) * 8;
    const int btcol = (lane >> 4) * 8;
    const uint32_t vBase = smB + 8704 + (uint32_t)btrow * 272 + (uint32_t)btcol * 2;

    const fp16* Qh = g_Qhi + (size_t)bh * HEAD_ELEMS + (size_t)q0 * DD;
    const fp16* Ql = g_Qlo + (size_t)bh * HEAD_ELEMS + (size_t)q0 * DD;
    const fp16* Kh = g_Khi + (size_t)bh * HEAD_ELEMS;
    const fp16* Vh = g_Vhi + (size_t)bh * HEAD_ELEMS;
    const fp16* Vl = g_Vlo + (size_t)bh * HEAD_ELEMS;

    uint32_t qa[8][8];
    {
        int ra = qb + g, rb2 = qb + g + 8;
#pragma unroll
        for (int kd = 0; kd < 8; kd++) {
            int c0 = kd * 16 + 2 * tg;
            qa[kd][0] = *reinterpret_cast<const uint32_t*>(Qh + ra  * 128 + c0);
            qa[kd][1] = *reinterpret_cast<const uint32_t*>(Qh + rb2 * 128 + c0);
            qa[kd][2] = *reinterpret_cast<const uint32_t*>(Qh + ra  * 128 + c0 + 8);
            qa[kd][3] = *reinterpret_cast<const uint32_t*>(Qh + rb2 * 128 + c0 + 8);
            qa[kd][4] = *reinterpret_cast<const uint32_t*>(Ql + ra  * 128 + c0);
            qa[kd][5] = *reinterpret_cast<const uint32_t*>(Ql + rb2 * 128 + c0);
            qa[kd][6] = *reinterpret_cast<const uint32_t*>(Ql + ra  * 128 + c0 + 8);
            qa[kd][7] = *reinterpret_cast<const uint32_t*>(Ql + rb2 * 128 + c0 + 8);
        }
    }

    auto prefetch = [&](int kt, int st) {
#pragma unroll
        for (int q = 0; q < 3; q++) {   // {Khi, Vhi, Vlo}
            const fp16* src = (q == 0) ? Kh : (q == 1) ? Vh : Vl;
            uint32_t sbase = smB + st * FL_STAGE + q * 8704;
#pragma unroll
            for (int j = 0; j < 4; j++) {
                int fi = t + 128 * j;          // 32 rows x 16 chunks
                int r = fi >> 4, i = fi & 15;
                cpa16(sbase + (r * 136 + i * 8) * 2,
                      src + (size_t)(kt * 32 + r) * 128 + i * 8);
            }
        }
    };

    float oc[16][4];
#pragma unroll
    for (int nt = 0; nt < 16; nt++)
#pragma unroll
        for (int i = 0; i < 4; i++) oc[nt][i] = 0.0f;
    float l0r = 0.0f, l1r = 0.0f;

    prefetch(0, 0);
    CP_COMMIT();

    for (int kt = 0; kt < 64; kt++) {
        int sb = kt & 1;
        __syncthreads();
        if (kt + 1 < 64) { prefetch(kt + 1, sb ^ 1); CP_COMMIT(); CP_WAIT1(); }
        else CP_WAIT0();
        __syncthreads();

        const uint32_t kS = kBase + sb * FL_STAGE;
        const uint32_t vS = vBase + sb * FL_STAGE;

        // ---- S = Q K^T : 16(q) x 32(kv), 2-term (Qh*Kh + Ql*Kh) ----
        float sc[4][4];
#pragma unroll
        for (int nt = 0; nt < 4; nt++)
#pragma unroll
            for (int i = 0; i < 4; i++) sc[nt][i] = 0.0f;

#pragma unroll
        for (int kd = 0; kd < 8; kd++) {
            uint32_t ah0 = qa[kd][0], ah1 = qa[kd][1], ah2 = qa[kd][2], ah3 = qa[kd][3];
            uint32_t al0 = qa[kd][4], al1 = qa[kd][5], al2 = qa[kd][6], al3 = qa[kd][7];
#pragma unroll
            for (int ntp = 0; ntp < 2; ntp++) {
                uint32_t h0, h1, h2, h3;
                ldsm4(h0, h1, h2, h3, kS + ntp * 4352 + kd * 32);
                MMA2A(sc[2*ntp],   ah0, ah1, ah2, ah3, al0, al1, al2, al3, h0, h1);
                MMA2A(sc[2*ntp+1], ah0, ah1, ah2, ah3, al0, al1, al2, al3, h2, h3);
            }
        }

        // ---- interleaved: softmax chunk then PV(kc), 2-term ----
#pragma unroll
        for (int kc = 0; kc < 2; kc++) {
            float e00 = fexp(sc[2*kc][0]);
            float e01 = fexp(sc[2*kc][1]);
            float e10 = fexp(sc[2*kc][2]);
            float e11 = fexp(sc[2*kc][3]);
            float f00 = fexp(sc[2*kc+1][0]);
            float f01 = fexp(sc[2*kc+1][1]);
            float f10 = fexp(sc[2*kc+1][2]);
            float f11 = fexp(sc[2*kc+1][3]);
            l0r += (e00 + e01) + (f00 + f01);
            l1r += (e10 + e11) + (f10 + f11);
            uint32_t a0 = pack_pair(e00, e01);
            uint32_t a1 = pack_pair(e10, e11);
            uint32_t a2 = pack_pair(f00, f01);
            uint32_t a3 = pack_pair(f10, f11);
#pragma unroll
            for (int ntp = 0; ntp < 8; ntp++) {
                uint32_t h0, h1, h2, h3, l0, l1, l2, l3;
                uint32_t vo = vS + kc * 4352 + ntp * 32;
                ldsm4t(h0, h1, h2, h3, vo);
                ldsm4t(l0, l1, l2, l3, vo + 8704);
                MMA2(oc[2*ntp],   a0, a1, a2, a3, h0, h1, l0, l1);
                MMA2(oc[2*ntp+1], a0, a1, a2, a3, h2, h3, l2, l3);
            }
        }
    }

    l0r += __shfl_xor_sync(0xffffffffu, l0r, 1);
    l0r += __shfl_xor_sync(0xffffffffu, l0r, 2);
    l1r += __shfl_xor_sync(0xffffffffu, l1r, 1);
    l1r += __shfl_xor_sync(0xffffffffu, l1r, 2);

    // epilogue: normalize, write X-hi
    const int b = bh >> 3, h = bh & 7;
    float inv0 = 1.0f / l0r;
    float inv1 = 1.0f / l1r;
    size_t Xo = (size_t)b * BATCH_ELEMS + (size_t)q0 * PP + h * DD;
    int r0 = qb + g;
#pragma unroll
    for (int nt = 0; nt < 16; nt++) {
        int cc = nt * 8 + 2 * tg;
        size_t F0 = Xo + (size_t)r0 * PP + cc;
        size_t F1 = Xo + (size_t)(r0 + 8) * PP + cc;
        *reinterpret_cast<uint32_t*>(g_Xhi + F0) =
            pack_pair(oc[nt][0] * inv0, oc[nt][1] * inv0);
        *reinterpret_cast<uint32_t*>(g_Xhi + F1) =
            pack_pair(oc[nt][2] * inv1, oc[nt][3] * inv1);
    }
}

// ---------------- launch ----------------
extern "C" void kernel_launch(void* const* d_in, const int* in_sizes, int n_in,
                              void* d_out, int out_size)
{
    const float* emb = (const float*)d_in[0];
    const float* W1  = (const float*)d_in[1];
    const float* W2  = (const float*)d_in[2];
    const float* W3  = (const float*)d_in[3];
    const float* Wo  = (const float*)d_in[4];
    float* out = (float*)d_out;
    (void)in_sizes; (void)n_in; (void)out_size;

    cudaFuncSetAttribute(qkv_gemm_kernel, cudaFuncAttributeMaxDynamicSharedMemorySize, GEMM_SMEM);
    cudaFuncSetAttribute(out_gemm_kernel, cudaFuncAttributeMaxDynamicSharedMemorySize, OUT_SMEM);
    cudaFuncSetAttribute(flash_kernel,    cudaFuncAttributeMaxDynamicSharedMemorySize, FL_BYTES);

    rope_table_kernel<<<512, 256>>>();                                        // 0
    decomp_all_kernel<<<(NELEM + 4 * EE * PP + 255) / 256, 256>>>(emb, W1, W2, W3, Wo); // 1
    qkv_gemm_kernel<<<dim3(8, 64, 3), 256, GEMM_SMEM>>>();                    // 2
    flash_kernel<<<dim3(32, 32), 128, FL_BYTES>>>();                          // 3  <- ncu window
    out_gemm_kernel<<<dim3(8, 8, 8), 256, OUT_SMEM>>>(out);                   // 4
}

// round 17
// speedup vs baseline: 1.2491x; 1.1212x over previous
#include <cuda_runtime.h>
#include <cuda_fp16.h>
#include <cstdint>

#define BB 4
#define SS 2048
#define EE 1024
#define PP 1024
#define HH 8
#define DD 128
#define HEAD_ELEMS (SS*DD)
#define BATCH_ELEMS (SS*PP)
#define NELEM (BB*SS*PP)
#define SOFTMAX_SCALE 0.3535533905932738f
#define EXP_C1 1.44269504f
#define EXP_C0 (-23.08312066f)   // -16 * log2(e)

typedef __half fp16;

__device__ fp16 g_Ehi[NELEM],  g_Elo[NELEM];
__device__ fp16 g_W1hi[EE*PP], g_W1lo[EE*PP];
__device__ fp16 g_W2hi[EE*PP], g_W2lo[EE*PP];
__device__ fp16 g_W3hi[EE*PP], g_W3lo[EE*PP];
__device__ fp16 g_Wohi[EE*PP];
__device__ fp16 g_Qhi[NELEM],  g_Qlo[NELEM];
__device__ fp16 g_Khi[NELEM];
__device__ fp16 g_Klo[NELEM];                   // written by 3-term K proj epilogue
__device__ fp16 g_Vhi[NELEM];                   // [bh][s][d]  (V-lo dropped)
__device__ fp16 g_Xhi[NELEM];                   // [b][s][p]
__device__ float g_cos[SS*64], g_sin[SS*64];

// ---------------- helpers ----------------
__device__ __forceinline__ uint32_t smem_u32(const void* p) {
    uint32_t a;
    asm("{ .reg .u64 t; cvta.to.shared.u64 t, %1; cvt.u32.u64 %0, t; }" : "=r"(a) : "l"(p));
    return a;
}

__device__ __forceinline__ void cpa16(uint32_t s, const void* g) {
    asm volatile("cp.async.cg.shared.global [%0], [%1], 16;" :: "r"(s), "l"(g));
}
#define CP_COMMIT() asm volatile("cp.async.commit_group;" ::: "memory")
#define CP_WAIT1()  asm volatile("cp.async.wait_group 1;" ::: "memory")
#define CP_WAIT0()  asm volatile("cp.async.wait_group 0;" ::: "memory")

__device__ __forceinline__ void split2(float x, fp16& h, fp16& l)
{
    h = __float2half_rn(x);
    l = __float2half_rn(x - __half2float(h));
}

__device__ __forceinline__ void split_pair(float a, float b, uint32_t& hp, uint32_t& lp)
{
    asm("cvt.rn.f16x2.f32 %0, %1, %2;" : "=r"(hp) : "f"(b), "f"(a));
    __half2 hh = *reinterpret_cast<__half2*>(&hp);
    float la = a - __half2float(__low2half(hh));
    float lb = b - __half2float(__high2half(hh));
    asm("cvt.rn.f16x2.f32 %0, %1, %2;" : "=r"(lp) : "f"(lb), "f"(la));
}

__device__ __forceinline__ uint32_t pack_pair(float a, float b)
{
    uint32_t r;
    asm("cvt.rn.f16x2.f32 %0, %1, %2;" : "=r"(r) : "f"(b), "f"(a));
    return r;
}

__device__ __forceinline__ float fexp(float s)
{
    float f = fmaf(s, EXP_C1, EXP_C0);
    float r;
    asm("ex2.approx.f32 %0, %1;" : "=f"(r) : "f"(f));
    return r;
}

__device__ __forceinline__ void ldsm4(uint32_t& r0, uint32_t& r1,
                                      uint32_t& r2, uint32_t& r3, uint32_t a)
{
    asm volatile("ldmatrix.sync.aligned.m8n8.x4.shared.b16 {%0,%1,%2,%3}, [%4];"
                 : "=r"(r0), "=r"(r1), "=r"(r2), "=r"(r3) : "r"(a));
}

__device__ __forceinline__ void ldsm4t(uint32_t& r0, uint32_t& r1,
                                       uint32_t& r2, uint32_t& r3, uint32_t a)
{
    asm volatile("ldmatrix.sync.aligned.m8n8.x4.trans.shared.b16 {%0,%1,%2,%3}, [%4];"
                 : "=r"(r0), "=r"(r1), "=r"(r2), "=r"(r3) : "r"(a));
}

__device__ __forceinline__ void mma_f16(float& c0, float& c1, float& c2, float& c3,
                                        uint32_t a0, uint32_t a1, uint32_t a2, uint32_t a3,
                                        uint32_t b0, uint32_t b1)
{
    asm volatile(
        "mma.sync.aligned.m16n8k16.row.col.f32.f16.f16.f32 "
        "{%0,%1,%2,%3}, {%4,%5,%6,%7}, {%8,%9}, {%0,%1,%2,%3};\n"
        : "+f"(c0), "+f"(c1), "+f"(c2), "+f"(c3)
        : "r"(a0), "r"(a1), "r"(a2), "r"(a3), "r"(b0), "r"(b1));
}

#define MMA3(C, AH0,AH1,AH2,AH3, AL0,AL1,AL2,AL3, BH0,BH1, BL0,BL1)          \
    do {                                                                      \
        mma_f16(C[0],C[1],C[2],C[3], AH0,AH1,AH2,AH3, BH0,BH1);               \
        mma_f16(C[0],C[1],C[2],C[3], AH0,AH1,AH2,AH3, BL0,BL1);               \
        mma_f16(C[0],C[1],C[2],C[3], AL0,AL1,AL2,AL3, BH0,BH1);               \
    } while (0)

#define MMA2(C, A0,A1,A2,A3, BH0,BH1, BL0,BL1)                                \
    do {                                                                      \
        mma_f16(C[0],C[1],C[2],C[3], A0,A1,A2,A3, BH0,BH1);                   \
        mma_f16(C[0],C[1],C[2],C[3], A0,A1,A2,A3, BL0,BL1);                   \
    } while (0)

#define MMA2A(C, AH0,AH1,AH2,AH3, AL0,AL1,AL2,AL3, B0,B1)                     \
    do {                                                                      \
        mma_f16(C[0],C[1],C[2],C[3], AH0,AH1,AH2,AH3, B0,B1);                 \
        mma_f16(C[0],C[1],C[2],C[3], AL0,AL1,AL2,AL3, B0,B1);                 \
    } while (0)

// ---------------- aux kernels ----------------
__global__ void rope_table_kernel()
{
    int idx = blockIdx.x * blockDim.x + threadIdx.x;
    if (idx >= SS * 64) return;
    int dp = idx & 63;
    int s2 = idx >> 6;
    double inv = exp(-0.14391156831212787 * (double)dp);   // ln(10000)/64
    double ang = (double)s2 * inv;
    double sd, cd;
    sincos(ang, &sd, &cd);
    g_cos[idx] = (float)cd;
    g_sin[idx] = (float)sd;
}

__global__ void decomp_all_kernel(const float* __restrict__ emb,
                                  const float* __restrict__ W1,
                                  const float* __restrict__ W2,
                                  const float* __restrict__ W3,
                                  const float* __restrict__ Wo)
{
    int i = blockIdx.x * blockDim.x + threadIdx.x;
    if (i < NELEM) { split2(emb[i], g_Ehi[i], g_Elo[i]); return; }
    int j = i - NELEM;
    if (j >= 4 * EE * PP) return;
    int w = j >> 20, k = j & 1048575;
    if (w == 3) { g_Wohi[k] = __float2half_rn(Wo[k]); return; }
    float v; fp16 *h, *l;
    if (w == 0)      { v = W1[k]; h = g_W1hi; l = g_W1lo; }
    else if (w == 1) { v = W2[k]; h = g_W2hi; l = g_W2lo; }
    else             { v = W3[k]; h = g_W3hi; l = g_W3lo; }
    split2(v, h[k], l[k]);
}

// ---------------- QKV GEMM mainloop (TERMS = 3 or 2) ----------------
#define GEMM_SMEM 81920

template<int TERMS>
__device__ __forceinline__ void gemm_main(const fp16* Ah, const fp16* Al,
                                          const fp16* Bh, const fp16* Bl,
                                          float acc[4][4][4])
{
    extern __shared__ fp16 smem[];
    const int t = threadIdx.x, w = t >> 5, lane = t & 31;
    const int wm = (w >> 2) * 64, wn = (w & 3) * 32;
    uint32_t smB = smem_u32(smem);

    const int arow  = lane & 15, ahalf = lane >> 4;
    const int brow  = ((lane & 16) >> 1) + (lane & 7);
    const int bhalf = (lane >> 3) & 1;
    const uint32_t aBase = smB + (uint32_t)(wm + arow) * 80 + (uint32_t)ahalf * 16;
    const uint32_t bBase = smB + 20480 + (uint32_t)(wn + brow) * 80 + (uint32_t)bhalf * 16;

#pragma unroll
    for (int mt = 0; mt < 4; mt++)
#pragma unroll
        for (int nt = 0; nt < 4; nt++)
#pragma unroll
            for (int i = 0; i < 4; i++) acc[mt][nt][i] = 0.0f;

    const fp16* gp[4] = {Ah, Al, Bh, Bl};

    auto prefetch = [&](int c, int st) {
        int k0 = c * 32;
#pragma unroll
        for (int p = 0; p < 4; p++) {
            if (TERMS == 2 && p == 1) continue;
#pragma unroll
            for (int j = 0; j < 2; j++) {
                int fi = t + 256 * j;
                int row = fi >> 2, c8 = (fi & 3) * 8;
                cpa16(smB + st * 40960 + p * 10240 + (row * 40 + c8) * 2,
                      gp[p] + (size_t)row * 1024 + k0 + c8);
            }
        }
    };

    prefetch(0, 0);
    CP_COMMIT();

    for (int c = 0; c < 32; c++) {
        int sb = c & 1;
        __syncthreads();
        if (c + 1 < 32) { prefetch(c + 1, sb ^ 1); CP_COMMIT(); CP_WAIT1(); }
        else CP_WAIT0();
        __syncthreads();
        uint32_t u0 = sb * 40960;
#pragma unroll
        for (int ks = 0; ks < 2; ks++) {
            uint32_t ah[4][4], al[4][4];
#pragma unroll
            for (int mt = 0; mt < 4; mt++) {
                uint32_t ao = aBase + u0 + mt * 1280 + ks * 32;
                ldsm4(ah[mt][0], ah[mt][1], ah[mt][2], ah[mt][3], ao);
                if (TERMS == 3)
                    ldsm4(al[mt][0], al[mt][1], al[mt][2], al[mt][3], ao + 10240);
            }
            uint32_t bh[4][2], bl[4][2];
#pragma unroll
            for (int ntp = 0; ntp < 2; ntp++) {
                uint32_t bo = bBase + u0 + ntp * 1280 + ks * 32;
                ldsm4(bh[2*ntp][0], bh[2*ntp][1], bh[2*ntp+1][0], bh[2*ntp+1][1], bo);
                ldsm4(bl[2*ntp][0], bl[2*ntp][1], bl[2*ntp+1][0], bl[2*ntp+1][1], bo + 10240);
            }
#pragma unroll
            for (int mt = 0; mt < 4; mt++)
#pragma unroll
                for (int nt = 0; nt < 4; nt++) {
                    if (TERMS == 3)
                        MMA3(acc[mt][nt],
                             ah[mt][0], ah[mt][1], ah[mt][2], ah[mt][3],
                             al[mt][0], al[mt][1], al[mt][2], al[mt][3],
                             bh[nt][0], bh[nt][1], bl[nt][0], bl[nt][1]);
                    else
                        MMA2(acc[mt][nt],
                             ah[mt][0], ah[mt][1], ah[mt][2], ah[mt][3],
                             bh[nt][0], bh[nt][1], bl[nt][0], bl[nt][1]);
                }
        }
    }
}

// QKV: z=0 Q (rope+scale+split, 3-term), z=1 K (3-term), z=2 V (2-term, hi-only store)
__global__ __launch_bounds__(256, 2) void qkv_gemm_kernel()
{
    const int z = blockIdx.z;
    const fp16 *Bh, *Bl;
    if (z == 0)      { Bh = g_W1hi; Bl = g_W1lo; }
    else if (z == 1) { Bh = g_W2hi; Bl = g_W2lo; }
    else             { Bh = g_W3hi; Bl = g_W3lo; }
    const int m0 = blockIdx.y * 128, n0 = blockIdx.x * 128;
    const int t = threadIdx.x, w = t >> 5, lane = t & 31;
    const int g = lane >> 2, tg = lane & 3;
    const int wm = (w >> 2) * 64, wn = (w & 3) * 32;

    float acc[4][4][4];
    if (z == 2) {
        gemm_main<2>(g_Ehi + (size_t)m0 * 1024, g_Elo + (size_t)m0 * 1024,
                     Bh + (size_t)n0 * 1024, Bl + (size_t)n0 * 1024, acc);
#pragma unroll
        for (int mt = 0; mt < 4; mt++) {
#pragma unroll
            for (int nt = 0; nt < 4; nt++) {
                int c = n0 + wn + nt * 8 + 2 * tg;
#pragma unroll
                for (int half = 0; half < 2; half++) {
                    int r = m0 + wm + mt * 16 + g + half * 8;
                    size_t F = (size_t)r * 1024 + c;
                    *reinterpret_cast<uint32_t*>(g_Vhi + F) =
                        pack_pair(acc[mt][nt][half*2], acc[mt][nt][half*2 + 1]);
                }
            }
        }
        return;
    }

    gemm_main<3>(g_Ehi + (size_t)m0 * 1024, g_Elo + (size_t)m0 * 1024,
                 Bh + (size_t)n0 * 1024, Bl + (size_t)n0 * 1024, acc);

    fp16* Dh = (z == 0) ? g_Qhi : g_Khi;
    fp16* Dl = (z == 0) ? g_Qlo : g_Klo;
    const float scale = (z == 0) ? SOFTMAX_SCALE : 1.0f;
#pragma unroll
    for (int mt = 0; mt < 4; mt++) {
#pragma unroll
        for (int nt = 0; nt < 4; nt++) {
            int c = n0 + wn + nt * 8 + 2 * tg;
            int dp = (c & 127) >> 1;
#pragma unroll
            for (int half = 0; half < 2; half++) {
                int r = m0 + wm + mt * 16 + g + half * 8;
                size_t F = (size_t)r * 1024 + c;
                int s2v = (int)((F >> 7) & 2047);
                int ti = s2v * 64 + dp;
                float cs = g_cos[ti], sn = g_sin[ti];
                float x = acc[mt][nt][half * 2], y = acc[mt][nt][half * 2 + 1];
                float rx = (x * cs - y * sn) * scale;
                float ry = (y * cs + x * sn) * scale;
                uint32_t hp, lp;
                split_pair(rx, ry, hp, lp);
                *reinterpret_cast<uint32_t*>(Dh + F) = hp;
                *reinterpret_cast<uint32_t*>(Dl + F) = lp;
            }
        }
    }
}

// ---------------- output GEMM (1-term fp16) ----------------
#define OUT_SMEM 37888

__global__ __launch_bounds__(256, 2) void out_gemm_kernel(float* __restrict__ out)
{
    extern __shared__ fp16 smem[];
    const size_t bc = blockIdx.z;
    const int m0 = blockIdx.y * 128, n0 = blockIdx.x * 128;
    const int t = threadIdx.x, w = t >> 5, lane = t & 31;
    const int g = lane >> 2, tg = lane & 3;
    const int wm = (w >> 2) * 64, wn = (w & 3) * 32;
    uint32_t smB = smem_u32(smem);

    const int arow  = lane & 15, ahalf = lane >> 4;
    const uint32_t aBase = smB + (uint32_t)(wm + arow) * 80 + (uint32_t)ahalf * 16;
    const int btrow = (lane & 7) + ((lane >> 3) & 1) * 8;
    const int btcol = (lane >> 4) * 8;
    const uint32_t bTBase = smB + 10240 + (uint32_t)btrow * 272 + (uint32_t)btcol * 2;

    const fp16* Ah = g_Wohi + (size_t)m0 * 1024;
    const fp16* Xh = g_Xhi + bc * 1048576;

    float acc[4][4][4];
#pragma unroll
    for (int mt = 0; mt < 4; mt++)
#pragma unroll
        for (int nt = 0; nt < 4; nt++)
#pragma unroll
            for (int i = 0; i < 4; i++) acc[mt][nt][i] = 0.0f;

    auto prefetch = [&](int c, int st) {
        int k0 = c * 32;
#pragma unroll
        for (int j = 0; j < 2; j++) {
            int fi = t + 256 * j;
            int row = fi >> 2, c8 = (fi & 3) * 8;
            cpa16(smB + st * 18944 + (row * 40 + c8) * 2,
                  Ah + (size_t)row * 1024 + k0 + c8);
        }
#pragma unroll
        for (int j = 0; j < 2; j++) {
            int fi = t + 256 * j;
            int row = fi >> 4, c8 = (fi & 15) * 8;
            cpa16(smB + st * 18944 + 10240 + (row * 136 + c8) * 2,
                  Xh + (size_t)(k0 + row) * 1024 + n0 + c8);
        }
    };

    prefetch(0, 0);
    CP_COMMIT();

    for (int c = 0; c < 32; c++) {
        int sb = c & 1;
        __syncthreads();
        if (c + 1 < 32) { prefetch(c + 1, sb ^ 1); CP_COMMIT(); CP_WAIT1(); }
        else CP_WAIT0();
        __syncthreads();
        uint32_t u0 = sb * 18944;
#pragma unroll
        for (int ks = 0; ks < 2; ks++) {
            uint32_t ah[4][4];
#pragma unroll
            for (int mt = 0; mt < 4; mt++) {
                uint32_t ao = aBase + u0 + mt * 1280 + ks * 32;
                ldsm4(ah[mt][0], ah[mt][1], ah[mt][2], ah[mt][3], ao);
            }
            uint32_t bh[4][2];
#pragma unroll
            for (int ntp = 0; ntp < 2; ntp++) {
                uint32_t bo = bTBase + u0 + ks * 4352 + (wn + ntp * 16) * 2;
                ldsm4t(bh[2*ntp][0], bh[2*ntp][1], bh[2*ntp+1][0], bh[2*ntp+1][1], bo);
            }
#pragma unroll
            for (int mt = 0; mt < 4; mt++)
#pragma unroll
                for (int nt = 0; nt < 4; nt++)
                    mma_f16(acc[mt][nt][0], acc[mt][nt][1], acc[mt][nt][2], acc[mt][nt][3],
                            ah[mt][0], ah[mt][1], ah[mt][2], ah[mt][3],
                            bh[nt][0], bh[nt][1]);
        }
    }

    float* Ob = out + bc * 1048576;
#pragma unroll
    for (int mt = 0; mt < 4; mt++) {
        int r0 = m0 + wm + mt * 16 + g;
#pragma unroll
        for (int nt = 0; nt < 4; nt++) {
            int cc = n0 + wn + nt * 8 + 2 * tg;
            *reinterpret_cast<float2*>(Ob + (size_t)r0 * PP + cc) =
                make_float2(acc[mt][nt][0], acc[mt][nt][1]);
            *reinterpret_cast<float2*>(Ob + (size_t)(r0 + 8) * PP + cc) =
                make_float2(acc[mt][nt][2], acc[mt][nt][3]);
        }
    }
}

// ---------------- flash attention: S 2-term (K hi), PV 1-term (V hi) ----------------
// 128 threads, 2 CTAs/SM, Br=64, Bc=32, 2-stage smem.
// stage st (17408 B): Khi@0, Vhi@8704.
#define FL_STAGE 17408
#define FL_BYTES (2 * FL_STAGE)   // 34816

__global__ __launch_bounds__(128, 2) void flash_kernel()
{
    extern __shared__ char sm[];
    const int bh = blockIdx.y, q0 = blockIdx.x * 64;
    const int t = threadIdx.x, w = t >> 5, lane = t & 31;
    const int g = lane >> 2, tg = lane & 3;
    const int qb = w * 16;
    uint32_t smB = smem_u32(sm);

    const int brow  = ((lane & 16) >> 1) + (lane & 7);
    const int bhalf = (lane >> 3) & 1;
    const uint32_t kBase = smB + (uint32_t)brow * 272 + (uint32_t)bhalf * 16;
    const int btrow = (lane & 7) + ((lane >> 3) & 1) * 8;
    const int btcol = (lane >> 4) * 8;
    const uint32_t vBase = smB + 8704 + (uint32_t)btrow * 272 + (uint32_t)btcol * 2;

    const fp16* Qh = g_Qhi + (size_t)bh * HEAD_ELEMS + (size_t)q0 * DD;
    const fp16* Ql = g_Qlo + (size_t)bh * HEAD_ELEMS + (size_t)q0 * DD;
    const fp16* Kh = g_Khi + (size_t)bh * HEAD_ELEMS;
    const fp16* Vh = g_Vhi + (size_t)bh * HEAD_ELEMS;

    uint32_t qa[8][8];
    {
        int ra = qb + g, rb2 = qb + g + 8;
#pragma unroll
        for (int kd = 0; kd < 8; kd++) {
            int c0 = kd * 16 + 2 * tg;
            qa[kd][0] = *reinterpret_cast<const uint32_t*>(Qh + ra  * 128 + c0);
            qa[kd][1] = *reinterpret_cast<const uint32_t*>(Qh + rb2 * 128 + c0);
            qa[kd][2] = *reinterpret_cast<const uint32_t*>(Qh + ra  * 128 + c0 + 8);
            qa[kd][3] = *reinterpret_cast<const uint32_t*>(Qh + rb2 * 128 + c0 + 8);
            qa[kd][4] = *reinterpret_cast<const uint32_t*>(Ql + ra  * 128 + c0);
            qa[kd][5] = *reinterpret_cast<const uint32_t*>(Ql + rb2 * 128 + c0);
            qa[kd][6] = *reinterpret_cast<const uint32_t*>(Ql + ra  * 128 + c0 + 8);
            qa[kd][7] = *reinterpret_cast<const uint32_t*>(Ql + rb2 * 128 + c0 + 8);
        }
    }

    auto prefetch = [&](int kt, int st) {
#pragma unroll
        for (int q = 0; q < 2; q++) {   // {Khi, Vhi}
            const fp16* src = (q == 0) ? Kh : Vh;
            uint32_t sbase = smB + st * FL_STAGE + q * 8704;
#pragma unroll
            for (int j = 0; j < 4; j++) {
                int fi = t + 128 * j;          // 32 rows x 16 chunks
                int r = fi >> 4, i = fi & 15;
                cpa16(sbase + (r * 136 + i * 8) * 2,
                      src + (size_t)(kt * 32 + r) * 128 + i * 8);
            }
        }
    };

    float oc[16][4];
#pragma unroll
    for (int nt = 0; nt < 16; nt++)
#pragma unroll
        for (int i = 0; i < 4; i++) oc[nt][i] = 0.0f;
    float l0r = 0.0f, l1r = 0.0f;

    prefetch(0, 0);
    CP_COMMIT();

    for (int kt = 0; kt < 64; kt++) {
        int sb = kt & 1;
        __syncthreads();
        if (kt + 1 < 64) { prefetch(kt + 1, sb ^ 1); CP_COMMIT(); CP_WAIT1(); }
        else CP_WAIT0();
        __syncthreads();

        const uint32_t kS = kBase + sb * FL_STAGE;
        const uint32_t vS = vBase + sb * FL_STAGE;

        // ---- S = Q K^T : 16(q) x 32(kv), 2-term (Qh*Kh + Ql*Kh) ----
        float sc[4][4];
#pragma unroll
        for (int nt = 0; nt < 4; nt++)
#pragma unroll
            for (int i = 0; i < 4; i++) sc[nt][i] = 0.0f;

#pragma unroll
        for (int kd = 0; kd < 8; kd++) {
            uint32_t ah0 = qa[kd][0], ah1 = qa[kd][1], ah2 = qa[kd][2], ah3 = qa[kd][3];
            uint32_t al0 = qa[kd][4], al1 = qa[kd][5], al2 = qa[kd][6], al3 = qa[kd][7];
#pragma unroll
            for (int ntp = 0; ntp < 2; ntp++) {
                uint32_t h0, h1, h2, h3;
                ldsm4(h0, h1, h2, h3, kS + ntp * 4352 + kd * 32);
                MMA2A(sc[2*ntp],   ah0, ah1, ah2, ah3, al0, al1, al2, al3, h0, h1);
                MMA2A(sc[2*ntp+1], ah0, ah1, ah2, ah3, al0, al1, al2, al3, h2, h3);
            }
        }

        // ---- interleaved: softmax chunk then PV(kc), 1-term ----
#pragma unroll
        for (int kc = 0; kc < 2; kc++) {
            float e00 = fexp(sc[2*kc][0]);
            float e01 = fexp(sc[2*kc][1]);
            float e10 = fexp(sc[2*kc][2]);
            float e11 = fexp(sc[2*kc][3]);
            float f00 = fexp(sc[2*kc+1][0]);
            float f01 = fexp(sc[2*kc+1][1]);
            float f10 = fexp(sc[2*kc+1][2]);
            float f11 = fexp(sc[2*kc+1][3]);
            l0r += (e00 + e01) + (f00 + f01);
            l1r += (e10 + e11) + (f10 + f11);
            uint32_t a0 = pack_pair(e00, e01);
            uint32_t a1 = pack_pair(e10, e11);
            uint32_t a2 = pack_pair(f00, f01);
            uint32_t a3 = pack_pair(f10, f11);
#pragma unroll
            for (int ntp = 0; ntp < 8; ntp++) {
                uint32_t h0, h1, h2, h3;
                ldsm4t(h0, h1, h2, h3, vS + kc * 4352 + ntp * 32);
                mma_f16(oc[2*ntp][0], oc[2*ntp][1], oc[2*ntp][2], oc[2*ntp][3],
                        a0, a1, a2, a3, h0, h1);
                mma_f16(oc[2*ntp+1][0], oc[2*ntp+1][1], oc[2*ntp+1][2], oc[2*ntp+1][3],
                        a0, a1, a2, a3, h2, h3);
            }
        }
    }

    l0r += __shfl_xor_sync(0xffffffffu, l0r, 1);
    l0r += __shfl_xor_sync(0xffffffffu, l0r, 2);
    l1r += __shfl_xor_sync(0xffffffffu, l1r, 1);
    l1r += __shfl_xor_sync(0xffffffffu, l1r, 2);

    // epilogue: normalize, write X-hi
    const int b = bh >> 3, h = bh & 7;
    float inv0 = 1.0f / l0r;
    float inv1 = 1.0f / l1r;
    size_t Xo = (size_t)b * BATCH_ELEMS + (size_t)q0 * PP + h * DD;
    int r0 = qb + g;
#pragma unroll
    for (int nt = 0; nt < 16; nt++) {
        int cc = nt * 8 + 2 * tg;
        size_t F0 = Xo + (size_t)r0 * PP + cc;
        size_t F1 = Xo + (size_t)(r0 + 8) * PP + cc;
        *reinterpret_cast<uint32_t*>(g_Xhi + F0) =
            pack_pair(oc[nt][0] * inv0, oc[nt][1] * inv0);
        *reinterpret_cast<uint32_t*>(g_Xhi + F1) =
            pack_pair(oc[nt][2] * inv1, oc[nt][3] * inv1);
    }
}

// ---------------- launch ----------------
extern "C" void kernel_launch(void* const* d_in, const int* in_sizes, int n_in,
                              void* d_out, int out_size)
{
    const float* emb = (const float*)d_in[0];
    const float* W1  = (const float*)d_in[1];
    const float* W2  = (const float*)d_in[2];
    const float* W3  = (const float*)d_in[3];
    const float* Wo  = (const float*)d_in[4];
    float* out = (float*)d_out;
    (void)in_sizes; (void)n_in; (void)out_size;

    cudaFuncSetAttribute(qkv_gemm_kernel, cudaFuncAttributeMaxDynamicSharedMemorySize, GEMM_SMEM);
    cudaFuncSetAttribute(out_gemm_kernel, cudaFuncAttributeMaxDynamicSharedMemorySize, OUT_SMEM);
    cudaFuncSetAttribute(flash_kernel,    cudaFuncAttributeMaxDynamicSharedMemorySize, FL_BYTES);

    rope_table_kernel<<<512, 256>>>();                                        // 0
    decomp_all_kernel<<<(NELEM + 4 * EE * PP + 255) / 256, 256>>>(emb, W1, W2, W3, Wo); // 1
    qkv_gemm_kernel<<<dim3(8, 64, 3), 256, GEMM_SMEM>>>();                    // 2
    flash_kernel<<<dim3(32, 32), 128, FL_BYTES>>>();                          // 3  <- ncu window
    out_gemm_kernel<<<dim3(8, 8, 8), 256, OUT_SMEM>>>(out);                   // 4
}